// round 1
// baseline (speedup 1.0000x reference)
#include <cuda_runtime.h>
#include <math.h>

// Problem constants
#define BATCH   512
#define IN_DIM  256
#define OUT_DIM 256
#define NB      11            // GRID_SIZE + K = 8 + 3 bases
#define FPI     12            // features per input dim: 11 bases + silu
#define KDIM    (IN_DIM*FPI)  // 3072

// Scratch (device globals; no allocation allowed)
__device__ float g_F [BATCH  * KDIM];  // F[b][k]  (6 MB)
__device__ float g_W2[OUT_DIM * KDIM]; // W2[o][k] (3 MB)

// ---------------------------------------------------------------------------
// Kernel 1: per (b,i) compute 11 cubic B-spline bases + silu(x)
// Uniform grid g_j = -1.75 + 0.25*j, j=0..14 (exactly representable in fp32)
// ---------------------------------------------------------------------------
__global__ __launch_bounds__(256) void feat_kernel(const float* __restrict__ x)
{
    int idx = blockIdx.x * blockDim.x + threadIdx.x;   // idx = b*256 + i
    if (idx >= BATCH * IN_DIM) return;
    float xv = x[idx];

    float b0[14];
#pragma unroll
    for (int j = 0; j < 14; ++j) {
        float gj  = -1.75f + 0.25f * j;
        float gj1 = -1.75f + 0.25f * (j + 1);
        b0[j] = (xv >= gj && xv < gj1) ? 1.0f : 0.0f;
    }
    float b1[13];
#pragma unroll
    for (int m = 0; m < 13; ++m) {
        float gm = -1.75f + 0.25f * m;
        b1[m] = (xv - gm) * 4.0f * b0[m] + ((gm + 0.50f) - xv) * 4.0f * b0[m + 1];
    }
    float b2[12];
#pragma unroll
    for (int m = 0; m < 12; ++m) {
        float gm = -1.75f + 0.25f * m;
        b2[m] = (xv - gm) * 2.0f * b1[m] + ((gm + 0.75f) - xv) * 2.0f * b1[m + 1];
    }
    float b3[11];
#pragma unroll
    for (int m = 0; m < 11; ++m) {
        float gm = -1.75f + 0.25f * m;
        const float inv = 1.0f / 0.75f;
        b3[m] = (xv - gm) * inv * b2[m] + ((gm + 1.0f) - xv) * inv * b2[m + 1];
    }
    float sil = xv / (1.0f + expf(-xv));

    float* o = &g_F[(size_t)idx * FPI];
    float4 v0 = make_float4(b3[0], b3[1], b3[2],  b3[3]);
    float4 v1 = make_float4(b3[4], b3[5], b3[6],  b3[7]);
    float4 v2 = make_float4(b3[8], b3[9], b3[10], sil);
    *(float4*)(o + 0) = v0;
    *(float4*)(o + 4) = v1;
    *(float4*)(o + 8) = v2;
}

// ---------------------------------------------------------------------------
// Kernel 2: combined weight W2[o][i*12+j] = uw*coef (j<11), rw (j=11)
// ---------------------------------------------------------------------------
__global__ __launch_bounds__(256) void w2_kernel(const float* __restrict__ coef,
                                                 const float* __restrict__ rw,
                                                 const float* __restrict__ uw)
{
    int idx = blockIdx.x * blockDim.x + threadIdx.x;   // idx = o*256 + i
    if (idx >= OUT_DIM * IN_DIM) return;
    float u = uw[idx];
    float r = rw[idx];
    const float* c = &coef[(size_t)idx * NB];
    float v[12];
#pragma unroll
    for (int j = 0; j < NB; ++j) v[j] = u * c[j];
    v[11] = r;
    float* o = &g_W2[(size_t)idx * FPI];
    *(float4*)(o + 0) = make_float4(v[0], v[1], v[2],  v[3]);
    *(float4*)(o + 4) = make_float4(v[4], v[5], v[6],  v[7]);
    *(float4*)(o + 8) = make_float4(v[8], v[9], v[10], v[11]);
}

// ---------------------------------------------------------------------------
// Kernel 3: split-K SGEMM  out[b][o] += F[b][:] . W2[o][:]
// Tiles: BM=64, BN=64, BK=32; KSPLIT=8 (384 K each); 256 threads, 4x4 micro.
// Grid = (4, 8, 8) = 256 blocks.
// ---------------------------------------------------------------------------
#define BM 64
#define BN 64
#define BK 32
#define KSPLIT 8
#define KPER (KDIM / KSPLIT)   // 384

__global__ __launch_bounds__(256) void gemm_splitk(float* __restrict__ out)
{
    __shared__ float As[BK][BM + 4];
    __shared__ float Bs[BK][BN + 4];

    const int n0 = blockIdx.x * BN;
    const int m0 = blockIdx.y * BM;
    const int k0 = blockIdx.z * KPER;

    const int tid = threadIdx.x;
    const int tx = tid & 15;        // 0..15 -> n
    const int ty = tid >> 4;        // 0..15 -> m

    const int lm = tid >> 3;        // 0..31 (row within half-tile)
    const int lk = (tid & 7) << 2;  // 0,4,...,28

    float acc[4][4];
#pragma unroll
    for (int i = 0; i < 4; ++i)
#pragma unroll
        for (int j = 0; j < 4; ++j) acc[i][j] = 0.0f;

    for (int kt = 0; kt < KPER; kt += BK) {
        const int kbase = k0 + kt;
        // load A tile (F), transpose into As[k][m]
#pragma unroll
        for (int p = 0; p < BM; p += 32) {
            const float4 v = *(const float4*)(&g_F[(size_t)(m0 + lm + p) * KDIM + kbase + lk]);
            As[lk + 0][lm + p] = v.x;
            As[lk + 1][lm + p] = v.y;
            As[lk + 2][lm + p] = v.z;
            As[lk + 3][lm + p] = v.w;
        }
        // load B tile (W2), transpose into Bs[k][n]
#pragma unroll
        for (int p = 0; p < BN; p += 32) {
            const float4 v = *(const float4*)(&g_W2[(size_t)(n0 + lm + p) * KDIM + kbase + lk]);
            Bs[lk + 0][lm + p] = v.x;
            Bs[lk + 1][lm + p] = v.y;
            Bs[lk + 2][lm + p] = v.z;
            Bs[lk + 3][lm + p] = v.w;
        }
        __syncthreads();

#pragma unroll
        for (int kk = 0; kk < BK; ++kk) {
            const float4 av = *(const float4*)(&As[kk][ty * 4]);
            const float4 bv = *(const float4*)(&Bs[kk][tx * 4]);
            acc[0][0] += av.x * bv.x; acc[0][1] += av.x * bv.y;
            acc[0][2] += av.x * bv.z; acc[0][3] += av.x * bv.w;
            acc[1][0] += av.y * bv.x; acc[1][1] += av.y * bv.y;
            acc[1][2] += av.y * bv.z; acc[1][3] += av.y * bv.w;
            acc[2][0] += av.z * bv.x; acc[2][1] += av.z * bv.y;
            acc[2][2] += av.z * bv.z; acc[2][3] += av.z * bv.w;
            acc[3][0] += av.w * bv.x; acc[3][1] += av.w * bv.y;
            acc[3][2] += av.w * bv.z; acc[3][3] += av.w * bv.w;
        }
        __syncthreads();
    }

#pragma unroll
    for (int i = 0; i < 4; ++i) {
        const int m = m0 + ty * 4 + i;
#pragma unroll
        for (int j = 0; j < 4; ++j) {
            const int n = n0 + tx * 4 + j;
            atomicAdd(&out[(size_t)m * OUT_DIM + n], acc[i][j]);
        }
    }
}

// ---------------------------------------------------------------------------
// Launch
// inputs (metadata order): x[512,256], coef[256,256,11], residual_weight[256,256],
//                          univariate_weight[256,256]; output fp32 [512,256]
// ---------------------------------------------------------------------------
extern "C" void kernel_launch(void* const* d_in, const int* in_sizes, int n_in,
                              void* d_out, int out_size)
{
    const float* x    = (const float*)d_in[0];
    const float* coef = (const float*)d_in[1];
    const float* rw   = (const float*)d_in[2];
    const float* uw   = (const float*)d_in[3];
    float* out = (float*)d_out;

    cudaMemsetAsync(out, 0, (size_t)BATCH * OUT_DIM * sizeof(float));
    feat_kernel<<<(BATCH * IN_DIM + 255) / 256, 256>>>(x);
    w2_kernel<<<(OUT_DIM * IN_DIM + 255) / 256, 256>>>(coef, rw, uw);
    gemm_splitk<<<dim3(OUT_DIM / BN, BATCH / BM, KSPLIT), 256>>>(out);
}

// round 5
// speedup vs baseline: 1.7833x; 1.7833x over previous
#include <cuda_runtime.h>
#include <cuda_bf16.h>
#include <math.h>
#include <stdint.h>

// ---------------------------------------------------------------------------
// Problem constants
// ---------------------------------------------------------------------------
#define BATCH   512
#define IN_DIM  256
#define OUT_DIM 256
#define NB      11
#define FPI     12
#define KD      (IN_DIM*FPI)     // 3072 per section
#define K2      (3*KD)           // 9216: A = hi|lo|hi, B = hi|hi|lo

// GEMM config
#define BM 128
#define BN 64
#define BK 64
#define SK 9
#define KPC (K2/SK)              // 1024
#define NCH (KPC/BK)             // 16 chunks per CTA

// Scratch (device globals)
__device__ __nv_bfloat16 g_A2[(size_t)BATCH   * K2];  // 9.4 MB
__device__ __nv_bfloat16 g_B2[(size_t)OUT_DIM * K2];  // 4.7 MB

// ---------------------------------------------------------------------------
// helpers
// ---------------------------------------------------------------------------
__device__ __forceinline__ uint32_t smem_u32(const void* p) {
    uint32_t a;
    asm("{ .reg .u64 t; cvta.to.shared.u64 t, %1; cvt.u32.u64 %0, t; }" : "=r"(a) : "l"(p));
    return a;
}
__device__ __forceinline__ void cp_async16(uint32_t dst, const void* src) {
    asm volatile("cp.async.cg.shared.global [%0], [%1], 16;" :: "r"(dst), "l"(src));
}
__device__ __forceinline__ void cp_commit() {
    asm volatile("cp.async.commit_group;");
}
__device__ __forceinline__ void cp_wait1() {
    asm volatile("cp.async.wait_group 1;");
}
__device__ __forceinline__ void ldsm_x4(uint32_t& r0, uint32_t& r1, uint32_t& r2, uint32_t& r3, uint32_t a) {
    asm volatile("ldmatrix.sync.aligned.m8n8.x4.shared.b16 {%0,%1,%2,%3}, [%4];"
                 : "=r"(r0), "=r"(r1), "=r"(r2), "=r"(r3) : "r"(a));
}
__device__ __forceinline__ void mma16816(float* d, const uint32_t* a, uint32_t b0, uint32_t b1) {
    asm volatile(
        "mma.sync.aligned.m16n8k16.row.col.f32.bf16.bf16.f32 "
        "{%0,%1,%2,%3}, {%4,%5,%6,%7}, {%8,%9}, {%0,%1,%2,%3};"
        : "+f"(d[0]), "+f"(d[1]), "+f"(d[2]), "+f"(d[3])
        : "r"(a[0]), "r"(a[1]), "r"(a[2]), "r"(a[3]), "r"(b0), "r"(b1));
}
__device__ __forceinline__ void bf_split(float v, __nv_bfloat16& hi, __nv_bfloat16& lo) {
    hi = __float2bfloat16(v);
    lo = __float2bfloat16(v - __bfloat162float(hi));
}

// ---------------------------------------------------------------------------
// Kernel 1 (merged prep): blocks [0,512) -> features, [512,768) -> weights
// ---------------------------------------------------------------------------
__global__ __launch_bounds__(256) void prep_kernel(const float* __restrict__ x,
                                                   const float* __restrict__ coef,
                                                   const float* __restrict__ rw,
                                                   const float* __restrict__ uw)
{
    if (blockIdx.x < 512) {
        // ---- features: 11 cubic B-spline bases + silu ----
        int idx = blockIdx.x * blockDim.x + threadIdx.x;   // b*256 + i
        float xv = x[idx];

        float b0[14];
#pragma unroll
        for (int j = 0; j < 14; ++j) {
            float gj = -1.75f + 0.25f * j;
            b0[j] = (xv >= gj && xv < gj + 0.25f) ? 1.0f : 0.0f;
        }
        float b1[13];
#pragma unroll
        for (int m = 0; m < 13; ++m) {
            float gm = -1.75f + 0.25f * m;
            b1[m] = (xv - gm) * 4.0f * b0[m] + ((gm + 0.50f) - xv) * 4.0f * b0[m + 1];
        }
        float b2[12];
#pragma unroll
        for (int m = 0; m < 12; ++m) {
            float gm = -1.75f + 0.25f * m;
            b2[m] = (xv - gm) * 2.0f * b1[m] + ((gm + 0.75f) - xv) * 2.0f * b1[m + 1];
        }
        float f[12];
#pragma unroll
        for (int m = 0; m < 11; ++m) {
            float gm = -1.75f + 0.25f * m;
            const float inv = 1.0f / 0.75f;
            f[m] = (xv - gm) * inv * b2[m] + ((gm + 1.0f) - xv) * inv * b2[m + 1];
        }
        f[11] = xv / (1.0f + __expf(-xv));

        union { __nv_bfloat16 h[12]; uint2 u[3]; } hi, lo;
#pragma unroll
        for (int j = 0; j < 12; ++j) bf_split(f[j], hi.h[j], lo.h[j]);

        int b = idx >> 8, i = idx & 255;
        __nv_bfloat16* row = &g_A2[(size_t)b * K2 + i * FPI];
        uint2* s0 = (uint2*)(row);
        uint2* s1 = (uint2*)(row + KD);
        uint2* s2 = (uint2*)(row + 2 * KD);
#pragma unroll
        for (int j = 0; j < 3; ++j) { s0[j] = hi.u[j]; s1[j] = lo.u[j]; s2[j] = hi.u[j]; }
    } else {
        // ---- weights: W[o][i*12+j] = uw*coef (j<11), rw (j=11) ----
        int idx = (blockIdx.x - 512) * blockDim.x + threadIdx.x;   // o*256 + i
        float u = uw[idx];
        const float* c = &coef[(size_t)idx * NB];
        float w[12];
#pragma unroll
        for (int j = 0; j < NB; ++j) w[j] = u * c[j];
        w[11] = rw[idx];

        union { __nv_bfloat16 h[12]; uint2 u2[3]; } hi, lo;
#pragma unroll
        for (int j = 0; j < 12; ++j) bf_split(w[j], hi.h[j], lo.h[j]);

        int o = idx >> 8, i = idx & 255;
        __nv_bfloat16* row = &g_B2[(size_t)o * K2 + i * FPI];
        uint2* s0 = (uint2*)(row);
        uint2* s1 = (uint2*)(row + KD);
        uint2* s2 = (uint2*)(row + 2 * KD);
#pragma unroll
        for (int j = 0; j < 3; ++j) { s0[j] = hi.u2[j]; s1[j] = hi.u2[j]; s2[j] = lo.u2[j]; }
    }
}

// ---------------------------------------------------------------------------
// Kernel 2: mma.sync bf16 GEMM, BM=128 BN=64 BK=64, split-K=9, atomics out
// grid = (N/BN=4, M/BM=4, SK=9) = 144 CTAs, 256 threads (8 warps, 4m x 2n)
// smem: per stage A 128x128B (swizzled) + B 64x128B; 2 stages = 48 KB
// B is stored [n][k] in smem == "col-major B" for row.col mma -> NON-trans
// ldmatrix gives the correct b-fragment (lane l: n=l>>2, k=(l&3)*2+{0,1}).
// ---------------------------------------------------------------------------
#define ATILE 16384
#define BTILE 8192
#define STAGE (ATILE + BTILE)     // 24576

__global__ __launch_bounds__(256, 1) void gemm_mma(float* __restrict__ out)
{
    __shared__ __align__(1024) char smem[2 * STAGE];
    const uint32_t sbase = smem_u32(smem);

    const int tid = threadIdx.x;
    const int wid = tid >> 5;
    const int lid = tid & 31;
    const int warp_m = wid & 3;       // 0..3 -> 32-row slice
    const int warp_n = wid >> 2;      // 0..1 -> 32-col slice

    const int n0 = blockIdx.x * BN;
    const int m0 = blockIdx.y * BM;
    const int k00 = blockIdx.z * KPC;

    const __nv_bfloat16* A = g_A2;
    const __nv_bfloat16* B = g_B2;

    // ---- async loader for chunk c into stage s ----
    auto load_stage = [&](int c, int s) {
        const int kb = k00 + c * BK;
        const uint32_t st = sbase + s * STAGE;
        // A: 1024 chunks of 16B; 4 per thread
#pragma unroll
        for (int t = 0; t < 4; ++t) {
            const int li = tid + 256 * t;
            const int r = li >> 3;
            const int cb = (li & 7) << 4;
            const uint32_t dst = st + r * 128 + (cb ^ ((r & 7) << 4));
            cp_async16(dst, A + (size_t)(m0 + r) * K2 + kb + (cb >> 1));
        }
        // B: 512 chunks; 2 per thread
#pragma unroll
        for (int t = 0; t < 2; ++t) {
            const int li = tid + 256 * t;
            const int r = li >> 3;
            const int cb = (li & 7) << 4;
            const uint32_t dst = st + ATILE + r * 128 + (cb ^ ((r & 7) << 4));
            cp_async16(dst, B + (size_t)(n0 + r) * K2 + kb + (cb >> 1));
        }
    };

    float acc[2][4][4];
#pragma unroll
    for (int i = 0; i < 2; ++i)
#pragma unroll
        for (int j = 0; j < 4; ++j)
#pragma unroll
            for (int q = 0; q < 4; ++q) acc[i][j][q] = 0.0f;

    load_stage(0, 0); cp_commit();
    load_stage(1, 1); cp_commit();

    for (int c = 0; c < NCH; ++c) {
        cp_wait1();
        __syncthreads();
        const uint32_t st = sbase + (c & 1) * STAGE;

#pragma unroll
        for (int ks = 0; ks < 4; ++ks) {
            // A fragments: two m16 tiles
            uint32_t af[2][4];
#pragma unroll
            for (int mt = 0; mt < 2; ++mt) {
                const int r = warp_m * 32 + mt * 16 + (lid & 15);
                const int cb = ks * 32 + ((lid >> 4) << 4);
                ldsm_x4(af[mt][0], af[mt][1], af[mt][2], af[mt][3],
                        st + r * 128 + (cb ^ ((r & 7) << 4)));
            }
            // B fragments: 4 n8 tiles via two x4 (NON-trans; smem is [n][k])
            uint32_t bf[8];
#pragma unroll
            for (int nt = 0; nt < 2; ++nt) {
                const int r = warp_n * 32 + nt * 16 + (lid & 7) + ((lid >> 4) << 3);
                const int cb = ks * 32 + (((lid >> 3) & 1) << 4);
                ldsm_x4(bf[nt * 4 + 0], bf[nt * 4 + 1], bf[nt * 4 + 2], bf[nt * 4 + 3],
                        st + ATILE + r * 128 + (cb ^ ((r & 7) << 4)));
            }
#pragma unroll
            for (int mt = 0; mt < 2; ++mt)
#pragma unroll
                for (int j = 0; j < 4; ++j)
                    mma16816(acc[mt][j], af[mt], bf[j * 2], bf[j * 2 + 1]);
        }
        __syncthreads();
        if (c + 2 < NCH) load_stage(c + 2, c & 1);
        cp_commit();
    }

    // epilogue: atomic accumulate into out
    const int row_base = m0 + warp_m * 32 + (lid >> 2);
    const int col_base = n0 + warp_n * 32 + (lid & 3) * 2;
#pragma unroll
    for (int mt = 0; mt < 2; ++mt) {
#pragma unroll
        for (int j = 0; j < 4; ++j) {
            const int cc = col_base + j * 8;
            float* p0 = &out[(size_t)(row_base + mt * 16) * OUT_DIM + cc];
            atomicAdd(p0 + 0, acc[mt][j][0]);
            atomicAdd(p0 + 1, acc[mt][j][1]);
            float* p1 = p0 + 8 * OUT_DIM;
            atomicAdd(p1 + 0, acc[mt][j][2]);
            atomicAdd(p1 + 1, acc[mt][j][3]);
        }
    }
}

// ---------------------------------------------------------------------------
// Launch
// ---------------------------------------------------------------------------
extern "C" void kernel_launch(void* const* d_in, const int* in_sizes, int n_in,
                              void* d_out, int out_size)
{
    const float* x    = (const float*)d_in[0];
    const float* coef = (const float*)d_in[1];
    const float* rw   = (const float*)d_in[2];
    const float* uw   = (const float*)d_in[3];
    float* out = (float*)d_out;

    cudaMemsetAsync(out, 0, (size_t)BATCH * OUT_DIM * sizeof(float));
    prep_kernel<<<768, 256>>>(x, coef, rw, uw);
    gemm_mma<<<dim3(OUT_DIM / BN, BATCH / BM, SK), 256>>>(out);
}

// round 6
// speedup vs baseline: 1.9817x; 1.1113x over previous
#include <cuda_runtime.h>
#include <cuda_bf16.h>
#include <math.h>
#include <stdint.h>

// ---------------------------------------------------------------------------
// Problem constants
// ---------------------------------------------------------------------------
#define BATCH   512
#define IN_DIM  256
#define OUT_DIM 256
#define NB      11
#define FPI     12
#define KD      (IN_DIM*FPI)     // 3072 per section
#define K2      (3*KD)           // 9216 logical: A = hi|lo|hi, B = hi|hi|lo
#define KS2     (2*KD)           // 6144 stored:  A = hi|lo,    B = hi|lo

// GEMM config
#define BM 128
#define BN 64
#define BK 64
#define SK 18                    // 18 splits of 512 logical K; 6 per section
#define KPC (K2/SK)              // 512
#define NCH (KPC/BK)             // 8 chunks per CTA

// Scratch (device globals) — dedup: only hi|lo stored per operand
__device__ __nv_bfloat16 g_A2[(size_t)BATCH   * KS2];  // 6.3 MB
__device__ __nv_bfloat16 g_B2[(size_t)OUT_DIM * KS2];  // 3.1 MB

// ---------------------------------------------------------------------------
// helpers
// ---------------------------------------------------------------------------
__device__ __forceinline__ uint32_t smem_u32(const void* p) {
    uint32_t a;
    asm("{ .reg .u64 t; cvta.to.shared.u64 t, %1; cvt.u32.u64 %0, t; }" : "=r"(a) : "l"(p));
    return a;
}
__device__ __forceinline__ void cp_async16(uint32_t dst, const void* src) {
    asm volatile("cp.async.cg.shared.global [%0], [%1], 16;" :: "r"(dst), "l"(src));
}
__device__ __forceinline__ void cp_commit() {
    asm volatile("cp.async.commit_group;");
}
__device__ __forceinline__ void cp_wait1() {
    asm volatile("cp.async.wait_group 1;");
}
__device__ __forceinline__ void ldsm_x4(uint32_t& r0, uint32_t& r1, uint32_t& r2, uint32_t& r3, uint32_t a) {
    asm volatile("ldmatrix.sync.aligned.m8n8.x4.shared.b16 {%0,%1,%2,%3}, [%4];"
                 : "=r"(r0), "=r"(r1), "=r"(r2), "=r"(r3) : "r"(a));
}
__device__ __forceinline__ void mma16816(float* d, const uint32_t* a, uint32_t b0, uint32_t b1) {
    asm volatile(
        "mma.sync.aligned.m16n8k16.row.col.f32.bf16.bf16.f32 "
        "{%0,%1,%2,%3}, {%4,%5,%6,%7}, {%8,%9}, {%0,%1,%2,%3};"
        : "+f"(d[0]), "+f"(d[1]), "+f"(d[2]), "+f"(d[3])
        : "r"(a[0]), "r"(a[1]), "r"(a[2]), "r"(a[3]), "r"(b0), "r"(b1));
}
__device__ __forceinline__ void bf_split(float v, __nv_bfloat16& hi, __nv_bfloat16& lo) {
    hi = __float2bfloat16(v);
    lo = __float2bfloat16(v - __bfloat162float(hi));
}

// ---------------------------------------------------------------------------
// Kernel 1 (merged prep): blocks [0,512) -> features, [512,768) -> weights
// stores hi section at [0,KD), lo section at [KD,2KD)
// ---------------------------------------------------------------------------
__global__ __launch_bounds__(256) void prep_kernel(const float* __restrict__ x,
                                                   const float* __restrict__ coef,
                                                   const float* __restrict__ rw,
                                                   const float* __restrict__ uw)
{
    if (blockIdx.x < 512) {
        // ---- features: 11 cubic B-spline bases + silu ----
        int idx = blockIdx.x * blockDim.x + threadIdx.x;   // b*256 + i
        float xv = x[idx];

        float b0[14];
#pragma unroll
        for (int j = 0; j < 14; ++j) {
            float gj = -1.75f + 0.25f * j;
            b0[j] = (xv >= gj && xv < gj + 0.25f) ? 1.0f : 0.0f;
        }
        float b1[13];
#pragma unroll
        for (int m = 0; m < 13; ++m) {
            float gm = -1.75f + 0.25f * m;
            b1[m] = (xv - gm) * 4.0f * b0[m] + ((gm + 0.50f) - xv) * 4.0f * b0[m + 1];
        }
        float b2[12];
#pragma unroll
        for (int m = 0; m < 12; ++m) {
            float gm = -1.75f + 0.25f * m;
            b2[m] = (xv - gm) * 2.0f * b1[m] + ((gm + 0.75f) - xv) * 2.0f * b1[m + 1];
        }
        float f[12];
#pragma unroll
        for (int m = 0; m < 11; ++m) {
            float gm = -1.75f + 0.25f * m;
            const float inv = 1.0f / 0.75f;
            f[m] = (xv - gm) * inv * b2[m] + ((gm + 1.0f) - xv) * inv * b2[m + 1];
        }
        f[11] = xv / (1.0f + __expf(-xv));

        union { __nv_bfloat16 h[12]; uint2 u[3]; } hi, lo;
#pragma unroll
        for (int j = 0; j < 12; ++j) bf_split(f[j], hi.h[j], lo.h[j]);

        int b = idx >> 8, i = idx & 255;
        __nv_bfloat16* row = &g_A2[(size_t)b * KS2 + i * FPI];
        uint2* s0 = (uint2*)(row);
        uint2* s1 = (uint2*)(row + KD);
#pragma unroll
        for (int j = 0; j < 3; ++j) { s0[j] = hi.u[j]; s1[j] = lo.u[j]; }
    } else {
        // ---- weights: W[o][i*12+j] = uw*coef (j<11), rw (j=11) ----
        int idx = (blockIdx.x - 512) * blockDim.x + threadIdx.x;   // o*256 + i
        float u = uw[idx];
        const float* c = &coef[(size_t)idx * NB];
        float w[12];
#pragma unroll
        for (int j = 0; j < NB; ++j) w[j] = u * c[j];
        w[11] = rw[idx];

        union { __nv_bfloat16 h[12]; uint2 u2[3]; } hi, lo;
#pragma unroll
        for (int j = 0; j < 12; ++j) bf_split(w[j], hi.h[j], lo.h[j]);

        int o = idx >> 8, i = idx & 255;
        __nv_bfloat16* row = &g_B2[(size_t)o * KS2 + i * FPI];
        uint2* s0 = (uint2*)(row);
        uint2* s1 = (uint2*)(row + KD);
#pragma unroll
        for (int j = 0; j < 3; ++j) { s0[j] = hi.u2[j]; s1[j] = lo.u2[j]; }
    }
}

// ---------------------------------------------------------------------------
// Kernel 2: mma.sync bf16 GEMM, BM=128 BN=64 BK=64, split-K=18, atomics out
// grid = (4, 4, 18) = 288 CTAs (2/SM), 256 threads (8 warps, 4m x 2n)
// Logical K sections: A = hi|lo|hi, B = hi|hi|lo, realized by per-CTA offset
// remap into the dedup'd [hi|lo] arrays (each 512-wide split sits wholly
// inside one section: zsec = z/6).
// ---------------------------------------------------------------------------
#define ATILE 16384
#define BTILE 8192
#define STAGE (ATILE + BTILE)     // 24576

__global__ __launch_bounds__(256, 2) void gemm_mma(float* __restrict__ out)
{
    __shared__ __align__(1024) char smem[2 * STAGE];
    const uint32_t sbase = smem_u32(smem);

    const int tid = threadIdx.x;
    const int wid = tid >> 5;
    const int lid = tid & 31;
    const int warp_m = wid & 3;       // 0..3 -> 32-row slice
    const int warp_n = wid >> 2;      // 0..1 -> 32-col slice

    const int n0 = blockIdx.x * BN;
    const int m0 = blockIdx.y * BM;

    // section remap: logical z -> stored K offsets
    const int zsec = blockIdx.z / 6;          // 0,1,2
    const int koff = (blockIdx.z % 6) * KPC;  // 0..2560
    const int kA0 = ((zsec == 1) ? KD : 0) + koff;  // A: hi|lo|hi
    const int kB0 = ((zsec == 2) ? KD : 0) + koff;  // B: hi|hi|lo

    const __nv_bfloat16* A = g_A2;
    const __nv_bfloat16* B = g_B2;

    // ---- async loader for chunk c into stage s ----
    auto load_stage = [&](int c, int s) {
        const uint32_t st = sbase + s * STAGE;
        const int kbA = kA0 + c * BK;
        const int kbB = kB0 + c * BK;
        // A: 1024 chunks of 16B; 4 per thread
#pragma unroll
        for (int t = 0; t < 4; ++t) {
            const int li = tid + 256 * t;
            const int r = li >> 3;
            const int cb = (li & 7) << 4;
            const uint32_t dst = st + r * 128 + (cb ^ ((r & 7) << 4));
            cp_async16(dst, A + (size_t)(m0 + r) * KS2 + kbA + (cb >> 1));
        }
        // B: 512 chunks; 2 per thread
#pragma unroll
        for (int t = 0; t < 2; ++t) {
            const int li = tid + 256 * t;
            const int r = li >> 3;
            const int cb = (li & 7) << 4;
            const uint32_t dst = st + ATILE + r * 128 + (cb ^ ((r & 7) << 4));
            cp_async16(dst, B + (size_t)(n0 + r) * KS2 + kbB + (cb >> 1));
        }
    };

    float acc[2][4][4];
#pragma unroll
    for (int i = 0; i < 2; ++i)
#pragma unroll
        for (int j = 0; j < 4; ++j)
#pragma unroll
            for (int q = 0; q < 4; ++q) acc[i][j][q] = 0.0f;

    load_stage(0, 0); cp_commit();
    load_stage(1, 1); cp_commit();

    for (int c = 0; c < NCH; ++c) {
        cp_wait1();
        __syncthreads();
        const uint32_t st = sbase + (c & 1) * STAGE;

#pragma unroll
        for (int ks = 0; ks < 4; ++ks) {
            // A fragments: two m16 tiles
            uint32_t af[2][4];
#pragma unroll
            for (int mt = 0; mt < 2; ++mt) {
                const int r = warp_m * 32 + mt * 16 + (lid & 15);
                const int cb = ks * 32 + ((lid >> 4) << 4);
                ldsm_x4(af[mt][0], af[mt][1], af[mt][2], af[mt][3],
                        st + r * 128 + (cb ^ ((r & 7) << 4)));
            }
            // B fragments: 4 n8 tiles via two x4 (NON-trans; smem is [n][k])
            uint32_t bf[8];
#pragma unroll
            for (int nt = 0; nt < 2; ++nt) {
                const int r = warp_n * 32 + nt * 16 + (lid & 7) + ((lid >> 4) << 3);
                const int cb = ks * 32 + (((lid >> 3) & 1) << 4);
                ldsm_x4(bf[nt * 4 + 0], bf[nt * 4 + 1], bf[nt * 4 + 2], bf[nt * 4 + 3],
                        st + ATILE + r * 128 + (cb ^ ((r & 7) << 4)));
            }
#pragma unroll
            for (int mt = 0; mt < 2; ++mt)
#pragma unroll
                for (int j = 0; j < 4; ++j)
                    mma16816(acc[mt][j], af[mt], bf[j * 2], bf[j * 2 + 1]);
        }
        __syncthreads();
        if (c + 2 < NCH) load_stage(c + 2, c & 1);
        cp_commit();
    }

    // epilogue: atomic accumulate into out
    const int row_base = m0 + warp_m * 32 + (lid >> 2);
    const int col_base = n0 + warp_n * 32 + (lid & 3) * 2;
#pragma unroll
    for (int mt = 0; mt < 2; ++mt) {
#pragma unroll
        for (int j = 0; j < 4; ++j) {
            const int cc = col_base + j * 8;
            float* p0 = &out[(size_t)(row_base + mt * 16) * OUT_DIM + cc];
            atomicAdd(p0 + 0, acc[mt][j][0]);
            atomicAdd(p0 + 1, acc[mt][j][1]);
            float* p1 = p0 + 8 * OUT_DIM;
            atomicAdd(p1 + 0, acc[mt][j][2]);
            atomicAdd(p1 + 1, acc[mt][j][3]);
        }
    }
}

// ---------------------------------------------------------------------------
// Launch
// ---------------------------------------------------------------------------
extern "C" void kernel_launch(void* const* d_in, const int* in_sizes, int n_in,
                              void* d_out, int out_size)
{
    const float* x    = (const float*)d_in[0];
    const float* coef = (const float*)d_in[1];
    const float* rw   = (const float*)d_in[2];
    const float* uw   = (const float*)d_in[3];
    float* out = (float*)d_out;

    cudaMemsetAsync(out, 0, (size_t)BATCH * OUT_DIM * sizeof(float));
    prep_kernel<<<768, 256>>>(x, coef, rw, uw);
    gemm_mma<<<dim3(OUT_DIM / BN, BATCH / BM, SK), 256>>>(out);
}

// round 7
// speedup vs baseline: 3.0855x; 1.5570x over previous
#include <cuda_runtime.h>
#include <cuda_fp16.h>
#include <math.h>
#include <stdint.h>

// ---------------------------------------------------------------------------
// Problem constants
// ---------------------------------------------------------------------------
#define BATCH   512
#define IN_DIM  256
#define OUT_DIM 256
#define NB      11
#define FPI     12
#define KDIM    (IN_DIM*FPI)     // 3072 (single-pass fp16)

// GEMM config
#define BM 128
#define BN 64
#define BK 64
#define SK 16
#define KPC (KDIM/SK)            // 192
#define NCH (KPC/BK)             // 3 chunks per CTA

// Scratch (device globals)
__device__ __half g_A[(size_t)BATCH   * KDIM];  // 3.1 MB
__device__ __half g_B[(size_t)OUT_DIM * KDIM];  // 1.5 MB

// ---------------------------------------------------------------------------
// helpers
// ---------------------------------------------------------------------------
__device__ __forceinline__ uint32_t smem_u32(const void* p) {
    uint32_t a;
    asm("{ .reg .u64 t; cvta.to.shared.u64 t, %1; cvt.u32.u64 %0, t; }" : "=r"(a) : "l"(p));
    return a;
}
__device__ __forceinline__ void cp_async16(uint32_t dst, const void* src) {
    asm volatile("cp.async.cg.shared.global [%0], [%1], 16;" :: "r"(dst), "l"(src));
}
__device__ __forceinline__ void cp_commit() {
    asm volatile("cp.async.commit_group;");
}
__device__ __forceinline__ void cp_wait1() {
    asm volatile("cp.async.wait_group 1;");
}
__device__ __forceinline__ void ldsm_x4(uint32_t& r0, uint32_t& r1, uint32_t& r2, uint32_t& r3, uint32_t a) {
    asm volatile("ldmatrix.sync.aligned.m8n8.x4.shared.b16 {%0,%1,%2,%3}, [%4];"
                 : "=r"(r0), "=r"(r1), "=r"(r2), "=r"(r3) : "r"(a));
}
__device__ __forceinline__ void mma16816(float* d, const uint32_t* a, uint32_t b0, uint32_t b1) {
    asm volatile(
        "mma.sync.aligned.m16n8k16.row.col.f32.f16.f16.f32 "
        "{%0,%1,%2,%3}, {%4,%5,%6,%7}, {%8,%9}, {%0,%1,%2,%3};"
        : "+f"(d[0]), "+f"(d[1]), "+f"(d[2]), "+f"(d[3])
        : "r"(a[0]), "r"(a[1]), "r"(a[2]), "r"(a[3]), "r"(b0), "r"(b1));
}

// ---------------------------------------------------------------------------
// Kernel 1 (merged prep): blocks [0,512) -> features, [512,768) -> weights
// single fp16 section per operand
// ---------------------------------------------------------------------------
__global__ __launch_bounds__(256) void prep_kernel(const float* __restrict__ x,
                                                   const float* __restrict__ coef,
                                                   const float* __restrict__ rw,
                                                   const float* __restrict__ uw)
{
    if (blockIdx.x < 512) {
        // ---- features: 11 cubic B-spline bases + silu ----
        int idx = blockIdx.x * blockDim.x + threadIdx.x;   // b*256 + i
        float xv = x[idx];

        float b0[14];
#pragma unroll
        for (int j = 0; j < 14; ++j) {
            float gj = -1.75f + 0.25f * j;
            b0[j] = (xv >= gj && xv < gj + 0.25f) ? 1.0f : 0.0f;
        }
        float b1[13];
#pragma unroll
        for (int m = 0; m < 13; ++m) {
            float gm = -1.75f + 0.25f * m;
            b1[m] = (xv - gm) * 4.0f * b0[m] + ((gm + 0.50f) - xv) * 4.0f * b0[m + 1];
        }
        float b2[12];
#pragma unroll
        for (int m = 0; m < 12; ++m) {
            float gm = -1.75f + 0.25f * m;
            b2[m] = (xv - gm) * 2.0f * b1[m] + ((gm + 0.75f) - xv) * 2.0f * b1[m + 1];
        }
        float f[12];
#pragma unroll
        for (int m = 0; m < 11; ++m) {
            float gm = -1.75f + 0.25f * m;
            const float inv = 1.0f / 0.75f;
            f[m] = (xv - gm) * inv * b2[m] + ((gm + 1.0f) - xv) * inv * b2[m + 1];
        }
        f[11] = xv / (1.0f + __expf(-xv));

        union { __half h[12]; uint2 u[3]; } hv;
#pragma unroll
        for (int j = 0; j < 12; ++j) hv.h[j] = __float2half_rn(f[j]);

        int b = idx >> 8, i = idx & 255;
        uint2* s = (uint2*)&g_A[(size_t)b * KDIM + i * FPI];
#pragma unroll
        for (int j = 0; j < 3; ++j) s[j] = hv.u[j];
    } else {
        // ---- weights: W[o][i*12+j] = uw*coef (j<11), rw (j=11) ----
        int idx = (blockIdx.x - 512) * blockDim.x + threadIdx.x;   // o*256 + i
        float u = uw[idx];
        const float* c = &coef[(size_t)idx * NB];
        float w[12];
#pragma unroll
        for (int j = 0; j < NB; ++j) w[j] = u * c[j];
        w[11] = rw[idx];

        union { __half h[12]; uint2 u2[3]; } hv;
#pragma unroll
        for (int j = 0; j < 12; ++j) hv.h[j] = __float2half_rn(w[j]);

        int o = idx >> 8, i = idx & 255;
        uint2* s = (uint2*)&g_B[(size_t)o * KDIM + i * FPI];
#pragma unroll
        for (int j = 0; j < 3; ++j) s[j] = hv.u2[j];
    }
}

// ---------------------------------------------------------------------------
// Kernel 2: mma.sync fp16 GEMM, BM=128 BN=64 BK=64, split-K=16, atomics out
// grid = (4, 4, 16) = 256 CTAs, 256 threads (8 warps, 4m x 2n)
// smem: per stage A 128x128B (swizzled) + B 64x128B; 2 stages = 48 KB
// ---------------------------------------------------------------------------
#define ATILE 16384
#define BTILE 8192
#define STAGE (ATILE + BTILE)     // 24576

__global__ __launch_bounds__(256, 2) void gemm_mma(float* __restrict__ out)
{
    __shared__ __align__(1024) char smem[2 * STAGE];
    const uint32_t sbase = smem_u32(smem);

    const int tid = threadIdx.x;
    const int wid = tid >> 5;
    const int lid = tid & 31;
    const int warp_m = wid & 3;       // 0..3 -> 32-row slice
    const int warp_n = wid >> 2;      // 0..1 -> 32-col slice

    const int n0 = blockIdx.x * BN;
    const int m0 = blockIdx.y * BM;
    const int k00 = blockIdx.z * KPC;

    const __half* A = g_A;
    const __half* B = g_B;

    // ---- async loader for chunk c into stage s ----
    auto load_stage = [&](int c, int s) {
        const uint32_t st = sbase + s * STAGE;
        const int kb = k00 + c * BK;
        // A: 1024 chunks of 16B; 4 per thread
#pragma unroll
        for (int t = 0; t < 4; ++t) {
            const int li = tid + 256 * t;
            const int r = li >> 3;
            const int cb = (li & 7) << 4;
            const uint32_t dst = st + r * 128 + (cb ^ ((r & 7) << 4));
            cp_async16(dst, A + (size_t)(m0 + r) * KDIM + kb + (cb >> 1));
        }
        // B: 512 chunks; 2 per thread
#pragma unroll
        for (int t = 0; t < 2; ++t) {
            const int li = tid + 256 * t;
            const int r = li >> 3;
            const int cb = (li & 7) << 4;
            const uint32_t dst = st + ATILE + r * 128 + (cb ^ ((r & 7) << 4));
            cp_async16(dst, B + (size_t)(n0 + r) * KDIM + kb + (cb >> 1));
        }
    };

    float acc[2][4][4];
#pragma unroll
    for (int i = 0; i < 2; ++i)
#pragma unroll
        for (int j = 0; j < 4; ++j)
#pragma unroll
            for (int q = 0; q < 4; ++q) acc[i][j][q] = 0.0f;

    load_stage(0, 0); cp_commit();
    load_stage(1, 1); cp_commit();

    for (int c = 0; c < NCH; ++c) {
        cp_wait1();
        __syncthreads();
        const uint32_t st = sbase + (c & 1) * STAGE;

#pragma unroll
        for (int ks = 0; ks < 4; ++ks) {
            // A fragments: two m16 tiles
            uint32_t af[2][4];
#pragma unroll
            for (int mt = 0; mt < 2; ++mt) {
                const int r = warp_m * 32 + mt * 16 + (lid & 15);
                const int cb = ks * 32 + ((lid >> 4) << 4);
                ldsm_x4(af[mt][0], af[mt][1], af[mt][2], af[mt][3],
                        st + r * 128 + (cb ^ ((r & 7) << 4)));
            }
            // B fragments: 4 n8 tiles via two x4 (NON-trans; smem is [n][k])
            uint32_t bf[8];
#pragma unroll
            for (int nt = 0; nt < 2; ++nt) {
                const int r = warp_n * 32 + nt * 16 + (lid & 7) + ((lid >> 4) << 3);
                const int cb = ks * 32 + (((lid >> 3) & 1) << 4);
                ldsm_x4(bf[nt * 4 + 0], bf[nt * 4 + 1], bf[nt * 4 + 2], bf[nt * 4 + 3],
                        st + ATILE + r * 128 + (cb ^ ((r & 7) << 4)));
            }
#pragma unroll
            for (int mt = 0; mt < 2; ++mt)
#pragma unroll
                for (int j = 0; j < 4; ++j)
                    mma16816(acc[mt][j], af[mt], bf[j * 2], bf[j * 2 + 1]);
        }
        __syncthreads();
        if (c + 2 < NCH) load_stage(c + 2, c & 1);
        cp_commit();
    }

    // epilogue: atomic accumulate into out
    const int row_base = m0 + warp_m * 32 + (lid >> 2);
    const int col_base = n0 + warp_n * 32 + (lid & 3) * 2;
#pragma unroll
    for (int mt = 0; mt < 2; ++mt) {
#pragma unroll
        for (int j = 0; j < 4; ++j) {
            const int cc = col_base + j * 8;
            float* p0 = &out[(size_t)(row_base + mt * 16) * OUT_DIM + cc];
            atomicAdd(p0 + 0, acc[mt][j][0]);
            atomicAdd(p0 + 1, acc[mt][j][1]);
            float* p1 = p0 + 8 * OUT_DIM;
            atomicAdd(p1 + 0, acc[mt][j][2]);
            atomicAdd(p1 + 1, acc[mt][j][3]);
        }
    }
}

// ---------------------------------------------------------------------------
// Launch
// ---------------------------------------------------------------------------
extern "C" void kernel_launch(void* const* d_in, const int* in_sizes, int n_in,
                              void* d_out, int out_size)
{
    const float* x    = (const float*)d_in[0];
    const float* coef = (const float*)d_in[1];
    const float* rw   = (const float*)d_in[2];
    const float* uw   = (const float*)d_in[3];
    float* out = (float*)d_out;

    cudaMemsetAsync(out, 0, (size_t)BATCH * OUT_DIM * sizeof(float));
    prep_kernel<<<768, 256>>>(x, coef, rw, uw);
    gemm_mma<<<dim3(OUT_DIM / BN, BATCH / BM, SK), 256>>>(out);
}

// round 9
// speedup vs baseline: 3.4317x; 1.1122x over previous
#include <cuda_runtime.h>
#include <cuda_fp16.h>
#include <math.h>
#include <stdint.h>

// ---------------------------------------------------------------------------
// Problem constants
// ---------------------------------------------------------------------------
#define BATCH   512
#define IN_DIM  256
#define OUT_DIM 256
#define NB      11
#define FPI     12
#define KDIM    (IN_DIM*FPI)     // 3072

// GEMM config
#define BM 128
#define BN 64
#define BK 64
#define SK 16
#define KPC (KDIM/SK)            // 192
#define NCH (KPC/BK)             // 3 chunks per CTA

// Scratch (device globals)
__device__ __half g_A[(size_t)BATCH   * KDIM];  // 3.1 MB
__device__ __half g_B[(size_t)OUT_DIM * KDIM];  // 1.5 MB

// ---------------------------------------------------------------------------
// helpers
// ---------------------------------------------------------------------------
__device__ __forceinline__ uint32_t smem_u32(const void* p) {
    uint32_t a;
    asm("{ .reg .u64 t; cvta.to.shared.u64 t, %1; cvt.u32.u64 %0, t; }" : "=r"(a) : "l"(p));
    return a;
}
__device__ __forceinline__ void cp_async16(uint32_t dst, const void* src) {
    asm volatile("cp.async.cg.shared.global [%0], [%1], 16;" :: "r"(dst), "l"(src));
}
__device__ __forceinline__ void cp_commit() {
    asm volatile("cp.async.commit_group;");
}
__device__ __forceinline__ void cp_wait1() {
    asm volatile("cp.async.wait_group 1;");
}
__device__ __forceinline__ void ldsm_x4(uint32_t& r0, uint32_t& r1, uint32_t& r2, uint32_t& r3, uint32_t a) {
    asm volatile("ldmatrix.sync.aligned.m8n8.x4.shared.b16 {%0,%1,%2,%3}, [%4];"
                 : "=r"(r0), "=r"(r1), "=r"(r2), "=r"(r3) : "r"(a));
}
__device__ __forceinline__ void mma16816(float* d, const uint32_t* a, uint32_t b0, uint32_t b1) {
    asm volatile(
        "mma.sync.aligned.m16n8k16.row.col.f32.f16.f16.f32 "
        "{%0,%1,%2,%3}, {%4,%5,%6,%7}, {%8,%9}, {%0,%1,%2,%3};"
        : "+f"(d[0]), "+f"(d[1]), "+f"(d[2]), "+f"(d[3])
        : "r"(a[0]), "r"(a[1]), "r"(a[2]), "r"(a[3]), "r"(b0), "r"(b1));
}

// ---------------------------------------------------------------------------
// Kernel 1 (merged prep): blocks [0,512) -> features (+ zero out), rest -> weights
// Closed-form local cubic B-spline: only 4 bases nonzero per x.
// ---------------------------------------------------------------------------
__global__ __launch_bounds__(256) void prep_kernel(const float* __restrict__ x,
                                                   const float* __restrict__ coef,
                                                   const float* __restrict__ rw,
                                                   const float* __restrict__ uw,
                                                   float* __restrict__ out)
{
    if (blockIdx.x < 512) {
        int idx = blockIdx.x * blockDim.x + threadIdx.x;   // b*256 + i
        out[idx] = 0.0f;                                    // fused output zeroing
        float xv = x[idx];

        // cell index and local coordinate on the uniform knot grid [-1.75, 1.75]
        float xs = (xv + 1.75f) * 4.0f;
        float fc = floorf(xs);
        int   c  = (int)fc;
        float t  = xs - fc;
        float it = 1.0f - t;
        float t2 = t * t, t3 = t2 * t;
        float w0 = it * it * it * (1.0f / 6.0f);
        float w1 = (3.0f * t3 - 6.0f * t2 + 4.0f) * (1.0f / 6.0f);
        float w2 = (-3.0f * t3 + 3.0f * t2 + 3.0f * t + 1.0f) * (1.0f / 6.0f);
        float w3 = t3 * (1.0f / 6.0f);
        bool in_range = (c >= 0 && c <= 13);

        float f[12];
#pragma unroll
        for (int j = 0; j < 11; ++j) {
            int p = j - c + 3;          // basis j holds weight w[p] when 0<=p<=3
            float w = (p == 0) ? w0 : (p == 1) ? w1 : (p == 2) ? w2 : w3;
            f[j] = (in_range && p >= 0 && p <= 3) ? w : 0.0f;
        }
        f[11] = xv / (1.0f + __expf(-xv));

        union { __half h[12]; uint2 u[3]; } hv;
#pragma unroll
        for (int j = 0; j < 12; ++j) hv.h[j] = __float2half_rn(f[j]);

        int b = idx >> 8, i = idx & 255;
        uint2* s = (uint2*)&g_A[(size_t)b * KDIM + i * FPI];
#pragma unroll
        for (int j = 0; j < 3; ++j) s[j] = hv.u[j];
    } else {
        int idx = (blockIdx.x - 512) * blockDim.x + threadIdx.x;   // o*256 + i
        float u = uw[idx];
        const float* c = &coef[(size_t)idx * NB];
        float w[12];
#pragma unroll
        for (int j = 0; j < NB; ++j) w[j] = u * c[j];
        w[11] = rw[idx];

        union { __half h[12]; uint2 u2[3]; } hv;
#pragma unroll
        for (int j = 0; j < 12; ++j) hv.h[j] = __float2half_rn(w[j]);

        int o = idx >> 8, i = idx & 255;
        uint2* s = (uint2*)&g_B[(size_t)o * KDIM + i * FPI];
#pragma unroll
        for (int j = 0; j < 3; ++j) s[j] = hv.u2[j];
    }
}

// ---------------------------------------------------------------------------
// Kernel 2: mma.sync fp16 GEMM, BM=128 BN=64 BK=64, split-K=16
// grid = (4, 4, 16) = 256 CTAs, 256 threads (8 warps, 4m x 2n)
// Epilogue: stage tile in smem, then float4 vector REDs (4x fewer lanes).
// ---------------------------------------------------------------------------
#define ATILE 16384
#define BTILE 8192
#define STAGE (ATILE + BTILE)     // 24576
#define EPI_STRIDE 68             // fp32 row stride for epilogue staging

__global__ __launch_bounds__(256, 2) void gemm_mma(float* __restrict__ out)
{
    __shared__ __align__(1024) char smem[2 * STAGE];
    const uint32_t sbase = smem_u32(smem);

    const int tid = threadIdx.x;
    const int wid = tid >> 5;
    const int lid = tid & 31;
    const int warp_m = wid & 3;       // 0..3 -> 32-row slice
    const int warp_n = wid >> 2;      // 0..1 -> 32-col slice

    const int n0 = blockIdx.x * BN;
    const int m0 = blockIdx.y * BM;
    const int k00 = blockIdx.z * KPC;

    const __half* A = g_A;
    const __half* B = g_B;

    auto load_stage = [&](int c, int s) {
        const uint32_t st = sbase + s * STAGE;
        const int kb = k00 + c * BK;
#pragma unroll
        for (int t = 0; t < 4; ++t) {
            const int li = tid + 256 * t;
            const int r = li >> 3;
            const int cb = (li & 7) << 4;
            const uint32_t dst = st + r * 128 + (cb ^ ((r & 7) << 4));
            cp_async16(dst, A + (size_t)(m0 + r) * KDIM + kb + (cb >> 1));
        }
#pragma unroll
        for (int t = 0; t < 2; ++t) {
            const int li = tid + 256 * t;
            const int r = li >> 3;
            const int cb = (li & 7) << 4;
            const uint32_t dst = st + ATILE + r * 128 + (cb ^ ((r & 7) << 4));
            cp_async16(dst, B + (size_t)(n0 + r) * KDIM + kb + (cb >> 1));
        }
    };

    float acc[2][4][4];
#pragma unroll
    for (int i = 0; i < 2; ++i)
#pragma unroll
        for (int j = 0; j < 4; ++j)
#pragma unroll
            for (int q = 0; q < 4; ++q) acc[i][j][q] = 0.0f;

    load_stage(0, 0); cp_commit();
    load_stage(1, 1); cp_commit();

    for (int c = 0; c < NCH; ++c) {
        cp_wait1();
        __syncthreads();
        const uint32_t st = sbase + (c & 1) * STAGE;

#pragma unroll
        for (int ks = 0; ks < 4; ++ks) {
            uint32_t af[2][4];
#pragma unroll
            for (int mt = 0; mt < 2; ++mt) {
                const int r = warp_m * 32 + mt * 16 + (lid & 15);
                const int cb = ks * 32 + ((lid >> 4) << 4);
                ldsm_x4(af[mt][0], af[mt][1], af[mt][2], af[mt][3],
                        st + r * 128 + (cb ^ ((r & 7) << 4)));
            }
            uint32_t bf[8];
#pragma unroll
            for (int nt = 0; nt < 2; ++nt) {
                const int r = warp_n * 32 + nt * 16 + (lid & 7) + ((lid >> 4) << 3);
                const int cb = ks * 32 + (((lid >> 3) & 1) << 4);
                ldsm_x4(bf[nt * 4 + 0], bf[nt * 4 + 1], bf[nt * 4 + 2], bf[nt * 4 + 3],
                        st + ATILE + r * 128 + (cb ^ ((r & 7) << 4)));
            }
#pragma unroll
            for (int mt = 0; mt < 2; ++mt)
#pragma unroll
                for (int j = 0; j < 4; ++j)
                    mma16816(acc[mt][j], af[mt], bf[j * 2], bf[j * 2 + 1]);
        }
        __syncthreads();
        if (c + 2 < NCH) load_stage(c + 2, c & 1);
        cp_commit();
    }

    // ---- epilogue: stage fp32 tile in smem, then float4 vector REDs ----
    __syncthreads();   // smem buffers are free now
    float* stile = (float*)smem;   // [128][EPI_STRIDE]; 128*68*4 = 34816 B
    {
        const int r0 = warp_m * 32 + (lid >> 2);
        const int c0 = warp_n * 32 + (lid & 3) * 2;
#pragma unroll
        for (int mt = 0; mt < 2; ++mt) {
#pragma unroll
            for (int j = 0; j < 4; ++j) {
                const int rr = r0 + mt * 16;
                const int cc = c0 + j * 8;
                stile[rr * EPI_STRIDE + cc]           = acc[mt][j][0];
                stile[rr * EPI_STRIDE + cc + 1]       = acc[mt][j][1];
                stile[(rr + 8) * EPI_STRIDE + cc]     = acc[mt][j][2];
                stile[(rr + 8) * EPI_STRIDE + cc + 1] = acc[mt][j][3];
            }
        }
    }
    __syncthreads();
#pragma unroll
    for (int q = 0; q < 8; ++q) {
        const int li = tid + 256 * q;      // 0..2047 float4 slots
        const int r  = li >> 4;            // 16 float4 per row
        const int cq = (li & 15) << 2;
        const float4 v = *(const float4*)&stile[r * EPI_STRIDE + cq];
        atomicAdd((float4*)&out[(size_t)(m0 + r) * OUT_DIM + n0 + cq], v);
    }
}

// ---------------------------------------------------------------------------
// Launch
// ---------------------------------------------------------------------------
extern "C" void kernel_launch(void* const* d_in, const int* in_sizes, int n_in,
                              void* d_out, int out_size)
{
    const float* x    = (const float*)d_in[0];
    const float* coef = (const float*)d_in[1];
    const float* rw   = (const float*)d_in[2];
    const float* uw   = (const float*)d_in[3];
    float* out = (float*)d_out;

    prep_kernel<<<768, 256>>>(x, coef, rw, uw, out);
    gemm_mma<<<dim3(OUT_DIM / BN, BATCH / BM, SK), 256>>>(out);
}